// round 1
// baseline (speedup 1.0000x reference)
#include <cuda_runtime.h>
#include <math.h>

#define BG 256
#define TT 64
#define PP 10
#define DD 128
#define HH 64
#define BT (BG*TT)   // 16384

// ---- device scratch (allocation-free) ----
__device__ float g_z[BT*PP*64];            // SGCN output z  [bt][p][64]   ~41.9MB
__device__ float g_gih[(size_t)BT*PP*256]; // gates_ih+bias  [bt][p][256] ~167.8MB
__device__ float g_WihT[PP*64*256];        // W_ih transposed [p][i][g]

__device__ __forceinline__ float sigmoidf_(float v){ return 1.0f/(1.0f + expf(-v)); }

// ------------------------------------------------------------------
// Kernel 0: transpose W_ih [P][4H][in] -> [P][in][4H]
// ------------------------------------------------------------------
__global__ void transpose_wih(const float* __restrict__ Wih){
    int idx = blockIdx.x*blockDim.x + threadIdx.x;
    if (idx >= PP*64*256) return;
    int p = idx / 16384; int rem = idx - p*16384;
    int i = rem >> 8; int g = rem & 255;
    g_WihT[idx] = Wih[p*16384 + g*64 + i];
}

// ------------------------------------------------------------------
// Kernel 1: SGCN. One block per (b,t). 256 threads.
// ------------------------------------------------------------------
__global__ __launch_bounds__(256) void sgcn_kernel(
    const float* __restrict__ x,
    const float* __restrict__ Apos, const float* __restrict__ Aneg,
    const float* __restrict__ Wpb,  const float* __restrict__ bpb,
    const float* __restrict__ Wnb,  const float* __restrict__ bnb,
    const float* __restrict__ Wpd,  const float* __restrict__ bpd,
    const float* __restrict__ Wnd,  const float* __restrict__ bnd)
{
    __shared__ float xs[PP*DD];        // 1280
    __shared__ float Asm[2][PP*PP];    // 200 (row-normalized)
    __shared__ float rs[2][PP];
    __shared__ float aggx[2*PP*DD];    // 2560
    // cat blocks: [0..3] = deep aggregations, [4]=h_pos, [5]=h_neg. 320 floats each.
    __shared__ float cat[6*PP*32];     // 1920
    __shared__ float part[4*2*PP*32];  // 2560 partials: [((q*2+s)*10+r)*32+col]

    const int bt  = blockIdx.x;
    const int tid = threadIdx.x;

    // load x tile (float4)
    {
        const float4* x4 = (const float4*)(x + (size_t)bt*PP*DD);
        float4* xs4 = (float4*)xs;
        for (int i = tid; i < PP*DD/4; i += 256) xs4[i] = x4[i];
    }
    // load adjacencies
    if (tid < 200){
        int s = tid/100, idx = tid - s*100;
        Asm[s][idx] = (s ? Aneg : Apos)[(size_t)bt*100 + idx];
    }
    __syncthreads();
    if (tid < 20){
        int s = tid/10, r = tid - s*10;
        float sum = 0.f;
        #pragma unroll
        for (int j=0;j<10;j++) sum += Asm[s][r*10+j];
        rs[s][r] = 1.0f/(sum + 1e-8f);
    }
    __syncthreads();
    if (tid < 200){
        int s = tid/100, idx = tid - s*100;
        Asm[s][idx] *= rs[s][idx/10];
    }
    __syncthreads();

    // aggx[s][r][d] = sum_j An_s[r][j] * x[j][d]
    for (int o = tid; o < 2*PP*DD; o += 256){
        int s = o / (PP*DD); int rem = o - s*(PP*DD);
        int r = rem / DD;    int d  = rem - r*DD;
        float sum = 0.f;
        #pragma unroll
        for (int j=0;j<10;j++) sum += Asm[s][r*10+j]*xs[j*DD+d];
        aggx[o] = sum;
    }
    __syncthreads();

    // base matmul: h_s = tanh(cat([agg_s, x]) @ W_s_base + b)  K=256
    {
        const int col = tid & 31;
        const int s   = (tid>>5) & 1;
        const int q   = tid>>6;          // 0..3, 64 k each
        const float* W = s ? Wnb : Wpb;
        float acc[10];
        #pragma unroll
        for (int r=0;r<10;r++) acc[r]=0.f;
        const int k0 = q*64;
        if (q < 2){
            for (int kk=0;kk<64;kk++){
                int k = k0+kk;
                float w = W[k*32+col];
                #pragma unroll
                for (int r=0;r<10;r++) acc[r] += aggx[s*1280 + r*128 + k]*w;
            }
        } else {
            for (int kk=0;kk<64;kk++){
                int k = k0+kk;
                float w = W[k*32+col];
                int kx = k - 128;
                #pragma unroll
                for (int r=0;r<10;r++) acc[r] += xs[r*128 + kx]*w;
            }
        }
        #pragma unroll
        for (int r=0;r<10;r++) part[((q*2+s)*10+r)*32+col] = acc[r];
    }
    __syncthreads();
    for (int o=tid; o<640; o+=256){
        int s = o/320, rem = o - s*320, r = rem>>5, col = rem&31;
        float v = (s ? bnb : bpb)[col];
        #pragma unroll
        for (int q=0;q<4;q++) v += part[((q*2+s)*10+r)*32+col];
        cat[(4+s)*320 + r*32 + col] = tanhf(v);
    }
    __syncthreads();

    // two deep layers, K=224 (7 x 32 blocks)
    for (int layer=0; layer<2; layer++){
        // deep aggregations into cat[0..3]: m = asign*2 + hsign
        for (int o=tid; o<1280; o+=256){
            int m = o/320, rem = o - m*320, r = rem>>5, c = rem&31;
            int as = m>>1, hsn = m&1;
            float sum = 0.f;
            #pragma unroll
            for (int j=0;j<10;j++) sum += Asm[as][r*10+j]*cat[(4+hsn)*320 + j*32 + c];
            cat[m*320 + r*32 + c] = sum;
        }
        __syncthreads();
        {
            const int col = tid & 31;
            const int s   = (tid>>5) & 1;
            const int q   = tid>>6;      // 0..3, 56 k each
            const float* W = (s ? Wnd : Wpd) + layer*224*32;
            float acc[10];
            #pragma unroll
            for (int r=0;r<10;r++) acc[r]=0.f;
            for (int kk=0;kk<56;kk++){
                int k = q*56 + kk;
                float w = W[k*32+col];
                int blk = k>>5, ko = k&31;
                const float* src = cat + ((blk<6) ? blk : (4+s))*320;
                #pragma unroll
                for (int r=0;r<10;r++) acc[r] += src[r*32+ko]*w;
            }
            #pragma unroll
            for (int r=0;r<10;r++) part[((q*2+s)*10+r)*32+col] = acc[r];
        }
        __syncthreads();
        for (int o=tid; o<640; o+=256){
            int s = o/320, rem = o - s*320, r = rem>>5, col = rem&31;
            float v = (s ? bnd : bpd)[layer*32+col];
            #pragma unroll
            for (int q=0;q<4;q++) v += part[((q*2+s)*10+r)*32+col];
            cat[(4+s)*320 + r*32 + col] = tanhf(v);
        }
        __syncthreads();
    }

    // write z = cat([h_pos, h_neg], -1)
    float* zo = g_z + (size_t)bt*PP*64;
    for (int o=tid; o<640; o+=256){
        int r = o>>6, c = o&63, s = c>>5, cc = c&31;
        zo[o] = cat[(4+s)*320 + r*32 + cc];
    }
}

// ------------------------------------------------------------------
// Kernel 2: gates_ih = z @ W_ih^T + (b_ih + b_hh), per player GEMM
// grid: (16384/32, P), 256 threads. 32-row tiles, 8x4 register block.
// ------------------------------------------------------------------
__global__ __launch_bounds__(256) void gih_kernel(
    const float* __restrict__ bih, const float* __restrict__ bhh)
{
    __shared__ float zs[32*64];  // 8KB tile of z rows

    const int p   = blockIdx.y;
    const int r0  = blockIdx.x * 32;
    const int tid = threadIdx.x;

    for (int i = tid; i < 2048; i += 256){
        int rr = i>>6, d = i&63;
        zs[i] = g_z[((size_t)(r0+rr)*10 + p)*64 + d];
    }
    __syncthreads();

    const int g0  = (tid & 63) * 4;   // 4 consecutive gate cols
    const int rr0 = (tid >> 6) * 8;   // 8 rows
    const float* Wt = g_WihT + p*16384;  // [i][g] layout

    float acc[8][4];
    #pragma unroll
    for (int r=0;r<8;r++){
        #pragma unroll
        for (int j=0;j<4;j++) acc[r][j]=0.f;
    }

    #pragma unroll
    for (int i0=0; i0<64; i0+=4){
        float4 w0 = *(const float4*)&Wt[(i0+0)*256 + g0];
        float4 w1 = *(const float4*)&Wt[(i0+1)*256 + g0];
        float4 w2 = *(const float4*)&Wt[(i0+2)*256 + g0];
        float4 w3 = *(const float4*)&Wt[(i0+3)*256 + g0];
        #pragma unroll
        for (int r=0;r<8;r++){
            float4 z4 = *(const float4*)&zs[(rr0+r)*64 + i0];
            acc[r][0] += z4.x*w0.x + z4.y*w1.x + z4.z*w2.x + z4.w*w3.x;
            acc[r][1] += z4.x*w0.y + z4.y*w1.y + z4.z*w2.y + z4.w*w3.y;
            acc[r][2] += z4.x*w0.z + z4.y*w1.z + z4.z*w2.z + z4.w*w3.z;
            acc[r][3] += z4.x*w0.w + z4.y*w1.w + z4.z*w2.w + z4.w*w3.w;
        }
    }

    float b0 = bih[p*256+g0+0] + bhh[p*256+g0+0];
    float b1 = bih[p*256+g0+1] + bhh[p*256+g0+1];
    float b2 = bih[p*256+g0+2] + bhh[p*256+g0+2];
    float b3 = bih[p*256+g0+3] + bhh[p*256+g0+3];

    #pragma unroll
    for (int r=0;r<8;r++){
        size_t bt = (size_t)(r0 + rr0 + r);
        float4 o = make_float4(acc[r][0]+b0, acc[r][1]+b1, acc[r][2]+b2, acc[r][3]+b3);
        *(float4*)&g_gih[(bt*10 + p)*256 + g0] = o;
    }
}

// ------------------------------------------------------------------
// Kernel 3: LSTM recurrence. One block per (b,p). 256 threads.
// Each thread owns gate g and keeps its W_hh row (64 floats) in registers.
// ------------------------------------------------------------------
__global__ __launch_bounds__(256) void lstm_kernel(
    const float* __restrict__ Whh, float* __restrict__ out)
{
    __shared__ float hs[64];
    __shared__ float cs[64];
    __shared__ float gsm[256];

    const int b = blockIdx.x / PP;
    const int p = blockIdx.x - b*PP;
    const int g = threadIdx.x;

    // load this gate's W_hh row into registers (W_hh is [p][g][k], k contiguous)
    float wreg[64];
    {
        const float* Wp = Whh + (size_t)p*16384 + g*64;
        #pragma unroll
        for (int k=0;k<64;k+=4){
            float4 w4 = *(const float4*)&Wp[k];
            wreg[k+0]=w4.x; wreg[k+1]=w4.y; wreg[k+2]=w4.z; wreg[k+3]=w4.w;
        }
    }
    if (g < 64){ hs[g]=0.f; cs[g]=0.f; }
    __syncthreads();

    for (int t=0; t<TT; t++){
        size_t bt = (size_t)b*TT + t;
        float acc = g_gih[(bt*10 + p)*256 + g];
        #pragma unroll
        for (int k0=0;k0<64;k0+=4){
            float4 hv = *(const float4*)&hs[k0];
            acc += wreg[k0+0]*hv.x + wreg[k0+1]*hv.y + wreg[k0+2]*hv.z + wreg[k0+3]*hv.w;
        }
        gsm[g] = acc;
        __syncthreads();
        if (g < 64){
            float ig = sigmoidf_(gsm[g]);
            float fg = sigmoidf_(gsm[64+g]);
            float gg = tanhf(gsm[128+g]);
            float og = sigmoidf_(gsm[192+g]);
            float c  = fg*cs[g] + ig*gg;
            float h  = og*tanhf(c);
            cs[g] = c; hs[g] = h;
            out[(bt*10 + p)*64 + g] = h;
        }
        __syncthreads();
    }
}

// ------------------------------------------------------------------
extern "C" void kernel_launch(void* const* d_in, const int* in_sizes, int n_in,
                              void* d_out, int out_size)
{
    const float* x    = (const float*)d_in[0];
    const float* Apos = (const float*)d_in[1];
    const float* Aneg = (const float*)d_in[2];
    const float* Wpb  = (const float*)d_in[3];
    const float* bpb  = (const float*)d_in[4];
    const float* Wnb  = (const float*)d_in[5];
    const float* bnb  = (const float*)d_in[6];
    const float* Wpd  = (const float*)d_in[7];
    const float* bpd  = (const float*)d_in[8];
    const float* Wnd  = (const float*)d_in[9];
    const float* bnd  = (const float*)d_in[10];
    const float* Wih  = (const float*)d_in[11];
    const float* Whh  = (const float*)d_in[12];
    const float* bih  = (const float*)d_in[13];
    const float* bhh  = (const float*)d_in[14];
    float* out = (float*)d_out;

    transpose_wih<<<(PP*64*256 + 255)/256, 256>>>(Wih);

    sgcn_kernel<<<BT, 256>>>(x, Apos, Aneg, Wpb, bpb, Wnb, bnb,
                             Wpd, bpd, Wnd, bnd);

    dim3 gg(BT/32, PP);
    gih_kernel<<<gg, 256>>>(bih, bhh);

    lstm_kernel<<<BG*PP, 256>>>(Whh, out);
}

// round 3
// speedup vs baseline: 1.5923x; 1.5923x over previous
#include <cuda_runtime.h>
#include <math.h>

#define BG 256
#define TT 64
#define PP 10
#define DD 128
#define HH 64
#define BT (BG*TT)   // 16384

// ---- device scratch (allocation-free) ----
__device__ float g_z[BT*PP*64];            // SGCN output z  [bt][p][64]
__device__ float g_gih[(size_t)BT*PP*256]; // gates_ih+bias  [bt][p][256]
__device__ float g_WihT[PP*64*256];        // W_ih transposed [p][i][g]

// fast, accurate-enough activations
__device__ __forceinline__ float tanh_mufu(float x){
    float y; asm("tanh.approx.f32 %0, %1;" : "=f"(y) : "f"(x)); return y;
}
__device__ __forceinline__ float sigmoid_fast(float v){
    return __fdividef(1.0f, 1.0f + __expf(-v));   // MUFU EX2 + RCP, ~1e-6 err
}
__device__ __forceinline__ float tanh_fast(float v){
    return __fdividef(2.0f, 1.0f + __expf(-2.0f*v)) - 1.0f;  // ~1e-6 err
}

// ------------------------------------------------------------------
// Kernel 0: transpose W_ih [P][4H][in] -> [P][in][4H]
// ------------------------------------------------------------------
__global__ void transpose_wih(const float* __restrict__ Wih){
    int idx = blockIdx.x*blockDim.x + threadIdx.x;
    if (idx >= PP*64*256) return;
    int p = idx / 16384; int rem = idx - p*16384;
    int i = rem >> 8; int g = rem & 255;
    g_WihT[idx] = Wih[p*16384 + g*64 + i];
}

// ------------------------------------------------------------------
// Kernel 1: SGCN. One block per (b,t). 256 threads. Vectorized LDS.
// ------------------------------------------------------------------
__global__ __launch_bounds__(256) void sgcn_kernel(
    const float* __restrict__ x,
    const float* __restrict__ Apos, const float* __restrict__ Aneg,
    const float* __restrict__ Wpb,  const float* __restrict__ bpb,
    const float* __restrict__ Wnb,  const float* __restrict__ bnb,
    const float* __restrict__ Wpd,  const float* __restrict__ bpd,
    const float* __restrict__ Wnd,  const float* __restrict__ bnd)
{
    __shared__ float xs[PP*DD];        // 1280
    __shared__ float Asm[2][PP*PP];    // normalized adjacencies
    __shared__ float rs[2][PP];
    __shared__ float aggx[2*PP*DD];    // 2560
    // cat blocks: [0..3]=deep aggs, [4]=h_pos, [5]=h_neg; each 10x32
    __shared__ float cat[6*PP*32];     // 1920
    __shared__ float part[4*2*PP*32];  // partials

    const int bt  = blockIdx.x;
    const int tid = threadIdx.x;

    {   // x tile (float4)
        const float4* x4 = (const float4*)(x + (size_t)bt*PP*DD);
        float4* xs4 = (float4*)xs;
        for (int i = tid; i < PP*DD/4; i += 256) xs4[i] = x4[i];
    }
    if (tid < 200){
        int s = tid/100, idx = tid - s*100;
        Asm[s][idx] = (s ? Aneg : Apos)[(size_t)bt*100 + idx];
    }
    __syncthreads();
    if (tid < 20){
        int s = tid/10, r = tid - s*10;
        float sum = 0.f;
        #pragma unroll
        for (int j=0;j<10;j++) sum += Asm[s][r*10+j];
        rs[s][r] = __fdividef(1.0f, sum + 1e-8f);
    }
    __syncthreads();
    if (tid < 200){
        int s = tid/100, idx = tid - s*100;
        Asm[s][idx] *= rs[s][idx/10];
    }
    __syncthreads();

    // aggx[s][r][:] = An_s[r] @ x   (float4 over d)
    {
        float4* ag4 = (float4*)aggx;
        const float4* xs4 = (const float4*)xs;
        for (int o = tid; o < 2*PP*32; o += 256){
            int s = o / 320; int rem = o - s*320;
            int r = rem >> 5; int d4 = rem & 31;
            float4 sum = make_float4(0.f,0.f,0.f,0.f);
            #pragma unroll
            for (int j=0;j<10;j++){
                float a = Asm[s][r*10+j];
                float4 xv = xs4[j*32 + d4];
                sum.x += a*xv.x; sum.y += a*xv.y; sum.z += a*xv.z; sum.w += a*xv.w;
            }
            ag4[o] = sum;
        }
    }
    __syncthreads();

    // base matmul: h_s = tanh(cat([agg_s, x]) @ W_s_base + b), K=256
    {
        const int col = tid & 31;
        const int s   = (tid>>5) & 1;
        const int q   = tid>>6;          // 0..3 -> 64 k each
        const float* W = s ? Wnb : Wpb;
        const float* src = (q < 2) ? (aggx + s*1280 + q*64) : (xs + (q-2)*64);
        float acc[10];
        #pragma unroll
        for (int r=0;r<10;r++) acc[r]=0.f;
        const int k0 = q*64;
        #pragma unroll 4
        for (int kk=0;kk<64;kk+=4){
            int k = k0+kk;
            float w0 = W[(k+0)*32+col];
            float w1 = W[(k+1)*32+col];
            float w2 = W[(k+2)*32+col];
            float w3 = W[(k+3)*32+col];
            #pragma unroll
            for (int r=0;r<10;r++){
                float4 a = *(const float4*)&src[r*128 + kk];
                acc[r] += a.x*w0 + a.y*w1 + a.z*w2 + a.w*w3;
            }
        }
        #pragma unroll
        for (int r=0;r<10;r++) part[((q*2+s)*10+r)*32+col] = acc[r];
    }
    __syncthreads();
    for (int o=tid; o<640; o+=256){
        int s = o/320, rem = o - s*320, r = rem>>5, col = rem&31;
        float v = (s ? bnb : bpb)[col];
        #pragma unroll
        for (int q=0;q<4;q++) v += part[((q*2+s)*10+r)*32+col];
        cat[(4+s)*320 + r*32 + col] = tanh_mufu(v);
    }
    __syncthreads();

    // two deep layers, K=224 (7 x 32 blocks)
    for (int layer=0; layer<2; layer++){
        // deep aggregations into cat[0..3] (float4 over c)
        for (int o=tid; o<320; o+=256){
            int m = o/80, rem = o - m*80, r = rem>>3, c4 = (rem&7)*4;
            int as = m>>1, hsn = m&1;
            float4 sum = make_float4(0.f,0.f,0.f,0.f);
            #pragma unroll
            for (int j=0;j<10;j++){
                float a = Asm[as][r*10+j];
                float4 h = *(const float4*)&cat[(4+hsn)*320 + j*32 + c4];
                sum.x += a*h.x; sum.y += a*h.y; sum.z += a*h.z; sum.w += a*h.w;
            }
            *(float4*)&cat[m*320 + r*32 + c4] = sum;
        }
        __syncthreads();
        {
            const int col = tid & 31;
            const int s   = (tid>>5) & 1;
            const int q   = tid>>6;      // 0..3 -> 56 k each
            const float* W = (s ? Wnd : Wpd) + layer*224*32;
            float acc[10];
            #pragma unroll
            for (int r=0;r<10;r++) acc[r]=0.f;
            #pragma unroll 2
            for (int kk=0;kk<56;kk+=4){
                int k = q*56 + kk;
                float w0 = W[(k+0)*32+col];
                float w1 = W[(k+1)*32+col];
                float w2 = W[(k+2)*32+col];
                float w3 = W[(k+3)*32+col];
                int blk = k>>5, ko = k&31;
                const float* src = cat + ((blk<6) ? blk : (4+s))*320 + ko;
                #pragma unroll
                for (int r=0;r<10;r++){
                    float4 a = *(const float4*)&src[r*32];
                    acc[r] += a.x*w0 + a.y*w1 + a.z*w2 + a.w*w3;
                }
            }
            #pragma unroll
            for (int r=0;r<10;r++) part[((q*2+s)*10+r)*32+col] = acc[r];
        }
        __syncthreads();
        for (int o=tid; o<640; o+=256){
            int s = o/320, rem = o - s*320, r = rem>>5, col = rem&31;
            float v = (s ? bnd : bpd)[layer*32+col];
            #pragma unroll
            for (int q=0;q<4;q++) v += part[((q*2+s)*10+r)*32+col];
            cat[(4+s)*320 + r*32 + col] = tanh_mufu(v);
        }
        __syncthreads();
    }

    // write z = cat([h_pos, h_neg], -1)
    float* zo = g_z + (size_t)bt*PP*64;
    for (int o=tid; o<640; o+=256){
        int r = o>>6, c = o&63, s = c>>5, cc = c&31;
        zo[o] = cat[(4+s)*320 + r*32 + cc];
    }
}

// ------------------------------------------------------------------
// Kernel 2: gates_ih = z @ W_ih^T + (b_ih + b_hh), per player GEMM
// ------------------------------------------------------------------
__global__ __launch_bounds__(256) void gih_kernel(
    const float* __restrict__ bih, const float* __restrict__ bhh)
{
    __shared__ float zs[32*64];

    const int p   = blockIdx.y;
    const int r0  = blockIdx.x * 32;
    const int tid = threadIdx.x;

    {
        float4* zs4 = (float4*)zs;
        for (int i = tid; i < 512; i += 256){
            int rr = i>>4, d4 = i&15;
            zs4[i] = *(const float4*)&g_z[((size_t)(r0+rr)*10 + p)*64 + d4*4];
        }
    }
    __syncthreads();

    const int g0  = (tid & 63) * 4;
    const int rr0 = (tid >> 6) * 8;
    const float* Wt = g_WihT + p*16384;

    float acc[8][4];
    #pragma unroll
    for (int r=0;r<8;r++){
        #pragma unroll
        for (int j=0;j<4;j++) acc[r][j]=0.f;
    }

    #pragma unroll 4
    for (int i0=0; i0<64; i0+=4){
        float4 w0 = *(const float4*)&Wt[(i0+0)*256 + g0];
        float4 w1 = *(const float4*)&Wt[(i0+1)*256 + g0];
        float4 w2 = *(const float4*)&Wt[(i0+2)*256 + g0];
        float4 w3 = *(const float4*)&Wt[(i0+3)*256 + g0];
        #pragma unroll
        for (int r=0;r<8;r++){
            float4 z4 = *(const float4*)&zs[(rr0+r)*64 + i0];
            acc[r][0] += z4.x*w0.x + z4.y*w1.x + z4.z*w2.x + z4.w*w3.x;
            acc[r][1] += z4.x*w0.y + z4.y*w1.y + z4.z*w2.y + z4.w*w3.y;
            acc[r][2] += z4.x*w0.z + z4.y*w1.z + z4.z*w2.z + z4.w*w3.z;
            acc[r][3] += z4.x*w0.w + z4.y*w1.w + z4.z*w2.w + z4.w*w3.w;
        }
    }

    float b0 = bih[p*256+g0+0] + bhh[p*256+g0+0];
    float b1 = bih[p*256+g0+1] + bhh[p*256+g0+1];
    float b2 = bih[p*256+g0+2] + bhh[p*256+g0+2];
    float b3 = bih[p*256+g0+3] + bhh[p*256+g0+3];

    #pragma unroll
    for (int r=0;r<8;r++){
        size_t bt = (size_t)(r0 + rr0 + r);
        float4 o = make_float4(acc[r][0]+b0, acc[r][1]+b1, acc[r][2]+b2, acc[r][3]+b3);
        *(float4*)&g_gih[(bt*10 + p)*256 + g0] = o;
    }
}

// ------------------------------------------------------------------
// Kernel 3: LSTM recurrence. One block per (p, 4-game chunk).
// Thread owns gate g (W_hh row in registers) for 4 games.
// grid MUST be PP * (BG/4) = 640 blocks.
// ------------------------------------------------------------------
__global__ __launch_bounds__(256) void lstm_kernel(
    const float* __restrict__ Whh, float* __restrict__ out)
{
    __shared__ float hs[4][64];
    __shared__ float gsm[4][256];

    const int p     = blockIdx.x >> 6;        // 0..9
    const int chunk = blockIdx.x & 63;        // 0..63
    const int b0    = chunk*4;
    const int gt    = threadIdx.x;
    const int gm    = gt >> 6;    // activation role: game 0..3
    const int j     = gt & 63;    // activation role: hidden idx

    float wreg[64];
    {
        const float* Wp = Whh + (size_t)p*16384 + gt*64;
        #pragma unroll
        for (int k=0;k<64;k+=4){
            float4 w4 = *(const float4*)&Wp[k];
            wreg[k+0]=w4.x; wreg[k+1]=w4.y; wreg[k+2]=w4.z; wreg[k+3]=w4.w;
        }
    }
    ((float*)hs)[gt] = 0.f;
    float creg = 0.f;
    __syncthreads();

    // prefetch t=0 gates
    float pf[4];
    #pragma unroll
    for (int g4=0; g4<4; g4++)
        pf[g4] = g_gih[((size_t)(b0+g4)*64*10 + p)*256 + gt];

    for (int t=0; t<TT; t++){
        float acc0 = pf[0], acc1 = pf[1], acc2 = pf[2], acc3 = pf[3];
        #pragma unroll
        for (int k0=0;k0<64;k0+=4){
            float4 h0 = *(const float4*)&hs[0][k0];
            float4 h1 = *(const float4*)&hs[1][k0];
            float4 h2 = *(const float4*)&hs[2][k0];
            float4 h3 = *(const float4*)&hs[3][k0];
            float w0 = wreg[k0], w1 = wreg[k0+1], w2 = wreg[k0+2], w3 = wreg[k0+3];
            acc0 += w0*h0.x + w1*h0.y + w2*h0.z + w3*h0.w;
            acc1 += w0*h1.x + w1*h1.y + w2*h1.z + w3*h1.w;
            acc2 += w0*h2.x + w1*h2.y + w2*h2.z + w3*h2.w;
            acc3 += w0*h3.x + w1*h3.y + w2*h3.z + w3*h3.w;
        }
        if (t < TT-1){
            #pragma unroll
            for (int g4=0; g4<4; g4++)
                pf[g4] = g_gih[(((size_t)(b0+g4)*64 + t+1)*10 + p)*256 + gt];
        }
        gsm[0][gt] = acc0; gsm[1][gt] = acc1; gsm[2][gt] = acc2; gsm[3][gt] = acc3;
        __syncthreads();
        {
            float ig = sigmoid_fast(gsm[gm][j]);
            float fg = sigmoid_fast(gsm[gm][64+j]);
            float gg = tanh_fast   (gsm[gm][128+j]);
            float og = sigmoid_fast(gsm[gm][192+j]);
            creg = fg*creg + ig*gg;
            float h = og*tanh_fast(creg);
            hs[gm][j] = h;
            size_t bt = (size_t)(b0+gm)*64 + t;
            out[(bt*10 + p)*64 + j] = h;
        }
        __syncthreads();
    }
}

// ------------------------------------------------------------------
extern "C" void kernel_launch(void* const* d_in, const int* in_sizes, int n_in,
                              void* d_out, int out_size)
{
    const float* x    = (const float*)d_in[0];
    const float* Apos = (const float*)d_in[1];
    const float* Aneg = (const float*)d_in[2];
    const float* Wpb  = (const float*)d_in[3];
    const float* bpb  = (const float*)d_in[4];
    const float* Wnb  = (const float*)d_in[5];
    const float* bnb  = (const float*)d_in[6];
    const float* Wpd  = (const float*)d_in[7];
    const float* bpd  = (const float*)d_in[8];
    const float* Wnd  = (const float*)d_in[9];
    const float* bnd  = (const float*)d_in[10];
    const float* Wih  = (const float*)d_in[11];
    const float* Whh  = (const float*)d_in[12];
    const float* bih  = (const float*)d_in[13];
    const float* bhh  = (const float*)d_in[14];
    float* out = (float*)d_out;

    transpose_wih<<<(PP*64*256 + 255)/256, 256>>>(Wih);

    sgcn_kernel<<<BT, 256>>>(x, Apos, Aneg, Wpb, bpb, Wnb, bnb,
                             Wpd, bpd, Wnd, bnd);

    dim3 gg(BT/32, PP);
    gih_kernel<<<gg, 256>>>(bih, bhh);

    lstm_kernel<<<PP*(BG/4), 256>>>(Whh, out);   // 640 blocks
}